// round 5
// baseline (speedup 1.0000x reference)
#include <cuda_runtime.h>
#include <cuda_fp16.h>

#define BB 4
#define LL 1024
#define DD 64
#define UU 32
#define TI 4

// Scratch (allocation-free): transposed half2-packed k' and packed q.
__device__ uint4    g_kpt[4*BB*LL];    // [(b*4+cc)*1024 + j] : u [cc*8..cc*8+7]
__device__ unsigned g_qh [BB*LL*16];   // row*16 + c : u-pair (2c, 2c+1)

__device__ __forceinline__ unsigned tanh2u(unsigned x) {
    unsigned y; asm("tanh.approx.f16x2 %0, %1;" : "=r"(y) : "r"(x)); return y;
}
__device__ __forceinline__ unsigned hadd2u(unsigned a, unsigned b) {
    __half2 r = __hadd2(reinterpret_cast<__half2&>(a), reinterpret_cast<__half2&>(b));
    return reinterpret_cast<unsigned&>(r);
}
__device__ __forceinline__ unsigned hfma2u(unsigned a, unsigned b, unsigned c) {
    __half2 r = __hfma2(reinterpret_cast<__half2&>(a), reinterpret_cast<__half2&>(b),
                        reinterpret_cast<__half2&>(c));
    return reinterpret_cast<unsigned&>(r);
}
__device__ __forceinline__ unsigned packh2(float a, float b) {
    __half2 h = __floats2half2_rn(a, b);
    return reinterpret_cast<unsigned&>(h);
}
__device__ __forceinline__ float2 h2f2(unsigned a) {
    return __half22float2(reinterpret_cast<__half2&>(a));
}
// Packed fp32x2 (Blackwell FFMA2 — only reachable via PTX)
__device__ __forceinline__ unsigned long long ffma2(
    unsigned long long a, unsigned long long b, unsigned long long c) {
    unsigned long long d;
    asm("fma.rn.f32x2 %0, %1, %2, %3;" : "=l"(d) : "l"(a), "l"(b), "l"(c));
    return d;
}
__device__ __forceinline__ unsigned long long bcast2(float p) {
    unsigned long long d;
    asm("mov.b64 %0, {%1, %1};" : "=l"(d) : "f"(p));
    return d;
}
__device__ __forceinline__ unsigned long long packf2(float a, float b) {
    unsigned long long d;
    asm("mov.b64 %0, {%1, %2};" : "=l"(d) : "f"(a), "f"(b));
    return d;
}

// ---------------------------------------------------------------------------
// Kernel 1: projections -> packed/transposed half scratch. 8 rows per block.
// ---------------------------------------------------------------------------
__global__ __launch_bounds__(256) void prep_kernel(
    const float* __restrict__ x,
    const float* __restrict__ Wt,
    const float* __restrict__ Wx,
    const float* __restrict__ bh)
{
    __shared__ float sWt[DD*UU];
    __shared__ float sWx[DD*UU];
    __shared__ float sx [8*DD];
    __shared__ float sq [8][UU];
    __shared__ float sk [8][UU];
    int t = threadIdx.x;
    for (int idx = t; idx < DD*UU; idx += 256) { sWt[idx] = Wt[idx]; sWx[idx] = Wx[idx]; }
    int row0 = blockIdx.x * 8;
    for (int idx = t; idx < 8*DD; idx += 256) sx[idx] = x[row0*DD + idx];
    __syncthreads();

    int r = t >> 5, u = t & 31;
    float aq = 0.f, ak = 0.f;
    #pragma unroll
    for (int d = 0; d < DD; d++) {
        float xv = sx[r*DD + d];
        aq = fmaf(xv, sWt[d*UU + u], aq);
        ak = fmaf(xv, sWx[d*UU + u], ak);
    }
    sq[r][u] = aq;
    sk[r][u] = ak + bh[u];
    __syncthreads();

    if (t < 128) {
        int rr = t >> 4, c = t & 15;
        g_qh[(row0 + rr)*16 + c] = packh2(sq[rr][2*c], sq[rr][2*c+1]);
    }
    if (t < 32) {
        int rr = t >> 2, cc = t & 3;
        int row = row0 + rr;
        int b = row >> 10, j = row & 1023;
        uint4 v;
        v.x = packh2(sk[rr][cc*8+0], sk[rr][cc*8+1]);
        v.y = packh2(sk[rr][cc*8+2], sk[rr][cc*8+3]);
        v.z = packh2(sk[rr][cc*8+4], sk[rr][cc*8+5]);
        v.w = packh2(sk[rr][cc*8+6], sk[rr][cc*8+7]);
        g_kpt[(b*4 + cc)*1024 + j] = v;
    }
}

// ---------------------------------------------------------------------------
// Kernel 2: fused scoring + softmax + value gather. 4 rows per block.
// Register-dieted (rolling 1-ahead kv prefetch) for 4 blocks/SM.
// ---------------------------------------------------------------------------
__global__ __launch_bounds__(256, 4) void attn_kernel(
    const float* __restrict__ x,
    const float* __restrict__ Wa,
    float* __restrict__ out)
{
    __shared__ float4   p_sh[LL];         // {p_row0..p_row3} per j  (16 KB)
    __shared__ float    vsh [TI*LL];      // partials: [r][g][d]     (16 KB)
    __shared__ float    redv[TI][8];
    __shared__ unsigned swa2[16];
    __shared__ unsigned sq2[TI][16];

    int t  = threadIdx.x;
    int bi = blockIdx.x;                  // 0..1023
    int b  = bi >> 8;
    int row0 = b*LL + (bi & 255)*TI;

    if (t < 16) swa2[t] = packh2(Wa[2*t], Wa[2*t+1]);
    if (t < 64) sq2[t >> 4][t & 15] = g_qh[(row0 + (t >> 4))*16 + (t & 15)];
    __syncthreads();

    const uint4* kp = g_kpt + (b*4)*1024;

    // --- Pass 1: e = sum_u Wa[u] tanh(q+k'), fp32 accum across chunks ------
    float acc_e[4][TI];                   // [jj][r]
    #pragma unroll
    for (int jj = 0; jj < 4; jj++)
        #pragma unroll
        for (int r = 0; r < TI; r++) acc_e[jj][r] = 0.f;

    uint4 kv = kp[t];                     // rolling 1-ahead prefetch
    #pragma unroll
    for (int cc = 0; cc < 4; cc++) {
        unsigned qc[TI][4], wc[4];
        #pragma unroll
        for (int k = 0; k < 4; k++) {
            wc[k] = swa2[cc*4 + k];
            #pragma unroll
            for (int r = 0; r < TI; r++) qc[r][k] = sq2[r][cc*4 + k];
        }
        #pragma unroll
        for (int jj = 0; jj < 4; jj++) {
            unsigned kw[4] = {kv.x, kv.y, kv.z, kv.w};
            int nit = cc*4 + jj + 1;
            if (nit < 16)
                kv = kp[(nit >> 2)*1024 + (nit & 3)*256 + t];
            #pragma unroll
            for (int r = 0; r < TI; r++) {
                unsigned hacc = 0u;
                #pragma unroll
                for (int k = 0; k < 4; k++)
                    hacc = hfma2u(tanh2u(hadd2u(qc[r][k], kw[k])), wc[k], hacc);
                float2 f = h2f2(hacc);
                acc_e[jj][r] += f.x + f.y;
            }
        }
    }

    float s[TI] = {0.f, 0.f, 0.f, 0.f};
    #pragma unroll
    for (int jj = 0; jj < 4; jj++) {
        float4 pj;
        float* pp = (float*)&pj;
        #pragma unroll
        for (int r = 0; r < TI; r++) {
            float ex = __expf(acc_e[jj][r]);   // |e| <= sum|Wa|: no max pass
            pp[r] = ex;
            s[r] += ex;
        }
        p_sh[jj*256 + t] = pj;
    }

    // --- block sum reduce (all rows) ----------------------------------------
    #pragma unroll
    for (int o = 16; o; o >>= 1)
        #pragma unroll
        for (int r = 0; r < TI; r++) s[r] += __shfl_xor_sync(0xffffffffu, s[r], o);
    if ((t & 31) == 0)
        #pragma unroll
        for (int r = 0; r < TI; r++) redv[r][t >> 5] = s[r];
    __syncthreads();                      // also orders p_sh for pass 2
    float inv[TI];
    #pragma unroll
    for (int r = 0; r < TI; r++) {
        float S = 0.f;
        #pragma unroll
        for (int w = 0; w < 8; w++) S += redv[r][w];
        inv[r] = 1.f / (S + 1e-8f);
    }

    // --- Pass 2: v[r][d] = sum_j p[r][j] * x[b,j,d] -------------------------
    int d4 = t & 15, g = t >> 4;          // 16 float4 d-lanes x 16 j-groups
    const float4* xb = (const float4*)(x + b*(LL*DD));
    unsigned long long a[TI][2];
    #pragma unroll
    for (int r = 0; r < TI; r++) { a[r][0] = 0ull; a[r][1] = 0ull; }

    #pragma unroll 4
    for (int jj = 0; jj < 64; jj++) {
        int j = jj*16 + g;                // adjacent lanes -> adjacent j rows
        float4 xv = xb[j*16 + d4];
        unsigned long long xlo = packf2(xv.x, xv.y);
        unsigned long long xhi = packf2(xv.z, xv.w);
        float4 pj = p_sh[j];
        float* pp = (float*)&pj;
        #pragma unroll
        for (int r = 0; r < TI; r++) {
            unsigned long long p2 = bcast2(pp[r]);
            a[r][0] = ffma2(p2, xlo, a[r][0]);
            a[r][1] = ffma2(p2, xhi, a[r][1]);
        }
    }
    #pragma unroll
    for (int r = 0; r < TI; r++) {
        float4 av;
        ((unsigned long long*)&av)[0] = a[r][0];
        ((unsigned long long*)&av)[1] = a[r][1];
        ((float4*)vsh)[r*256 + g*16 + d4] = av;
    }
    __syncthreads();

    // --- final combine: 256 threads = 4 rows x 64 d -------------------------
    {
        int r = t >> 6, d = t & 63;
        float v = 0.f;
        #pragma unroll
        for (int gg = 0; gg < 16; gg++) v += vsh[r*LL + gg*64 + d];
        out[(row0 + r)*DD + d] = v * inv[r];
    }
}

// ---------------------------------------------------------------------------
extern "C" void kernel_launch(void* const* d_in, const int* in_sizes, int n_in,
                              void* d_out, int out_size)
{
    const float* x  = (const float*)d_in[0];
    const float* Wt = (const float*)d_in[1];
    const float* Wx = (const float*)d_in[2];
    const float* Wa = (const float*)d_in[3];
    const float* bh = (const float*)d_in[4];
    // d_in[5] = ba cancels in softmax; d_in[6] attention_width is dead code.

    prep_kernel<<<BB*LL/8, 256>>>(x, Wt, Wx, bh);
    attn_kernel<<<BB*LL/TI, 256>>>(x, Wa, (float*)d_out);
}